// round 1
// baseline (speedup 1.0000x reference)
#include <cuda_runtime.h>
#include <math.h>

#define H 1024
#define V 50257
#define S 4096

// ---------------- scratch (__device__ globals, no allocation) ----------------
__device__ float g_gi[3 * H];
__device__ float g_gh[3 * H];
__device__ float g_h[H];
__device__ float g_vpart[16][H];   // partials for v = attn_w^T @ h  (16 j-chunks of 64)
__device__ float g_v[H];
__device__ float g_scores[S];
__device__ float g_w[S];           // softmax weights
__device__ float g_ctxpart[32][H]; // partials for context (32 s-chunks of 128)
__device__ float g_ctx[H];

// ---------------- helpers ----------------
__device__ __forceinline__ float warp_sum(float v) {
#pragma unroll
    for (int o = 16; o; o >>= 1) v += __shfl_xor_sync(0xffffffffu, v, o);
    return v;
}

// ---------------- K1: gates  gi = w_ih @ x + b_ih ; gh = w_hh @ h_prev + b_hh
// grid = 6144 blocks of 256 threads; one block per output row.
__global__ void k_gates(const int* __restrict__ word,
                        const float* __restrict__ last_hidden,
                        const float* __restrict__ emb,
                        const float* __restrict__ w_ih,
                        const float* __restrict__ w_hh,
                        const float* __restrict__ b_ih,
                        const float* __restrict__ b_hh) {
    int b = blockIdx.x;
    const float* W;
    const float* vec;
    float bias;
    float* out;
    if (b < 3 * H) {
        int row = b;
        W = w_ih + (long)row * H;
        vec = emb + (long)word[0] * H;
        bias = b_ih[row];
        out = &g_gi[row];
    } else {
        int row = b - 3 * H;
        W = w_hh + (long)row * H;
        vec = last_hidden;
        bias = b_hh[row];
        out = &g_gh[row];
    }
    int t = threadIdx.x; // 256 threads * float4 = 1024 elems
    float4 a = reinterpret_cast<const float4*>(W)[t];
    float4 x = reinterpret_cast<const float4*>(vec)[t];
    float s = a.x * x.x + a.y * x.y + a.z * x.z + a.w * x.w;

    s = warp_sum(s);
    __shared__ float sm[8];
    int w = t >> 5, l = t & 31;
    if (!l) sm[w] = s;
    __syncthreads();
    if (w == 0) {
        s = (l < 8) ? sm[l] : 0.f;
#pragma unroll
        for (int o = 4; o; o >>= 1) s += __shfl_xor_sync(0xffffffffu, s, o);
        if (!l) *out = s + bias;
    }
}

// ---------------- K2: GRU combine, writes hidden output. 1 block x 1024.
__global__ void k_gru(const float* __restrict__ last_hidden, float* __restrict__ dout) {
    int i = threadIdx.x;
    float hp = last_hidden[i];
    float r = 1.f / (1.f + expf(-(g_gi[i] + g_gh[i])));
    float z = 1.f / (1.f + expf(-(g_gi[H + i] + g_gh[H + i])));
    float n = tanhf(g_gi[2 * H + i] + r * g_gh[2 * H + i]);
    float h = (1.f - z) * n + z * hp;
    g_h[i] = h;
    dout[V + i] = h; // hidden output slot
}

// ---------------- K3: v partials: v[c] = sum_j attn_w[j][c] * h[j]
// grid (4 col-chunks, 16 j-chunks of 64), 256 threads.
__global__ void k_vpart(const float* __restrict__ attn_w) {
    int c = blockIdx.x * 256 + threadIdx.x;
    int jc = blockIdx.y;
    float s = 0.f;
    const float* base = attn_w + (long)(jc * 64) * H + c;
#pragma unroll 8
    for (int j = 0; j < 64; j++)
        s += base[(long)j * H] * g_h[jc * 64 + j];
    g_vpart[jc][c] = s;
}

// ---------------- K4: reduce v partials. 1 block x 1024.
__global__ void k_vred() {
    int c = threadIdx.x;
    float s = 0.f;
#pragma unroll
    for (int j = 0; j < 16; j++) s += g_vpart[j][c];
    g_v[c] = s;
}

// ---------------- K5: scores[s] = enc[s] . v   (attn_b drops out of softmax)
// grid 512 blocks x 256 threads, warp per score (8 scores/block).
__global__ void k_scores(const float* __restrict__ enc) {
    int warp = threadIdx.x >> 5, lane = threadIdx.x & 31;
    int s = blockIdx.x * 8 + warp;
    const float4* er = reinterpret_cast<const float4*>(enc + (long)s * H);
    const float4* vr = reinterpret_cast<const float4*>(g_v);
    float acc = 0.f;
#pragma unroll
    for (int it = 0; it < 8; it++) {
        float4 e = er[it * 32 + lane];
        float4 v = vr[it * 32 + lane];
        acc += e.x * v.x + e.y * v.y + e.z * v.z + e.w * v.w;
    }
    acc = warp_sum(acc);
    if (!lane) g_scores[s] = acc;
}

// ---------------- K6: softmax over 4096 scores, writes attn_weights output.
// 1 block x 1024, 4 scores/thread.
__global__ void k_softmax(float* __restrict__ dout) {
    __shared__ float sm[32];
    __shared__ float bc;
    int t = threadIdx.x, w = t >> 5, l = t & 31;
    float x[4];
    float m = -INFINITY;
#pragma unroll
    for (int k = 0; k < 4; k++) {
        x[k] = g_scores[t * 4 + k];
        m = fmaxf(m, x[k]);
    }
#pragma unroll
    for (int o = 16; o; o >>= 1) m = fmaxf(m, __shfl_xor_sync(0xffffffffu, m, o));
    if (!l) sm[w] = m;
    __syncthreads();
    if (w == 0) {
        m = sm[l];
#pragma unroll
        for (int o = 16; o; o >>= 1) m = fmaxf(m, __shfl_xor_sync(0xffffffffu, m, o));
        if (!l) bc = m;
    }
    __syncthreads();
    m = bc;
    float e[4];
    float sum = 0.f;
#pragma unroll
    for (int k = 0; k < 4; k++) {
        e[k] = expf(x[k] - m);
        sum += e[k];
    }
    sum = warp_sum(sum);
    __syncthreads();
    if (!l) sm[w] = sum;
    __syncthreads();
    if (w == 0) {
        sum = sm[l];
        sum = warp_sum(sum);
        if (!l) bc = sum;
    }
    __syncthreads();
    float inv = 1.f / bc;
#pragma unroll
    for (int k = 0; k < 4; k++) {
        float wt = e[k] * inv;
        g_w[t * 4 + k] = wt;
        dout[V + H + t * 4 + k] = wt; // attn_weights output slot
    }
}

// ---------------- K7: context partials: ctx[c] = sum_s w[s]*enc[s][c]
// grid (4 col-chunks, 32 s-chunks of 128), 256 threads.
__global__ void k_ctxpart(const float* __restrict__ enc) {
    int c = blockIdx.x * 256 + threadIdx.x;
    int sc = blockIdx.y;
    float acc = 0.f;
    const float* base = enc + (long)(sc * 128) * H + c;
#pragma unroll 8
    for (int s = 0; s < 128; s++)
        acc += g_w[sc * 128 + s] * base[(long)s * H];
    g_ctxpart[sc][c] = acc;
}

// ---------------- K8: reduce context partials. 1 block x 1024.
__global__ void k_ctxred() {
    int c = threadIdx.x;
    float s = 0.f;
#pragma unroll
    for (int j = 0; j < 32; j++) s += g_ctxpart[j][c];
    g_ctx[c] = s;
}

// ---------------- K9: logits[r] = [h;ctx] . out_w[r] + out_b[r]
// warp per row, 8 rows/block, 6283 blocks x 256. The 412MB read — HBM bound.
__global__ void k_logits(const float* __restrict__ out_w,
                         const float* __restrict__ out_b,
                         float* __restrict__ dout) {
    __shared__ float4 cat[512]; // 2048 floats = [h | ctx]
    int t = threadIdx.x;
    cat[t] = reinterpret_cast<const float4*>(g_h)[t];
    cat[256 + t] = reinterpret_cast<const float4*>(g_ctx)[t];
    __syncthreads();

    int warp = t >> 5, lane = t & 31;
    int r = blockIdx.x * 8 + warp;
    if (r >= V) return;
    const float4* wr = reinterpret_cast<const float4*>(out_w + (long)r * (2 * H));
    float acc = 0.f;
#pragma unroll
    for (int it = 0; it < 16; it++) {
        float4 w = wr[it * 32 + lane];
        float4 c = cat[it * 32 + lane];
        acc += w.x * c.x + w.y * c.y + w.z * c.z + w.w * c.w;
    }
    acc = warp_sum(acc);
    if (!lane) dout[r] = acc + out_b[r];
}

// ---------------- launch ----------------
extern "C" void kernel_launch(void* const* d_in, const int* in_sizes, int n_in,
                              void* d_out, int out_size) {
    const int* word = (const int*)d_in[0];
    const float* last_hidden = (const float*)d_in[1];
    const float* enc = (const float*)d_in[2];
    const float* emb = (const float*)d_in[3];
    const float* w_ih = (const float*)d_in[4];
    const float* w_hh = (const float*)d_in[5];
    const float* b_ih = (const float*)d_in[6];
    const float* b_hh = (const float*)d_in[7];
    const float* attn_w = (const float*)d_in[8];
    // d_in[9] = attn_b : constant shift before softmax -> mathematically no-op
    const float* out_w = (const float*)d_in[10];
    const float* out_b = (const float*)d_in[11];
    float* dout = (float*)d_out;

    k_gates<<<6 * H, 256>>>(word, last_hidden, emb, w_ih, w_hh, b_ih, b_hh);
    k_gru<<<1, 1024>>>(last_hidden, dout);
    k_vpart<<<dim3(4, 16), 256>>>(attn_w);
    k_vred<<<1, 1024>>>();
    k_scores<<<S / 8, 256>>>(enc);
    k_softmax<<<1, 1024>>>(dout);
    k_ctxpart<<<dim3(4, 32), 256>>>(enc);
    k_ctxred<<<1, 1024>>>();
    k_logits<<<(V + 7) / 8, 256>>>(out_w, out_b, dout);
}